// round 3
// baseline (speedup 1.0000x reference)
#include <cuda_runtime.h>

#define BB 64
#define SS 512
#define HH 768
#define TTAG 17
#define TPOS 45
#define MM (BB*SS)
#define MAXT 45

// ---- scratch (no allocations allowed) ----
__device__ float g_tag[MM*TTAG];   // [B*S, 17] raw tag logits
__device__ float g_pos[MM*TPOS];   // [B*S, 45] raw pos logits
__device__ float g_diff[2*BB];     // per-(head,batch) num-den

// ============================================================
// GEMM: logits = hidden @ [W_tag | W_pos] + bias
// 128 tokens x 62 cols per block, K-chunks of 32
// ============================================================
__global__ __launch_bounds__(256) void gemm_kernel(
    const float* __restrict__ hidden,
    const float* __restrict__ Wt, const float* __restrict__ bt,
    const float* __restrict__ Wp, const float* __restrict__ bp)
{
    __shared__ float Hs[128*36];   // 128 tokens x 32 k (pad 36)
    __shared__ float Ws[32*64];    // 32 k x 62 cols (pad 64)
    const int tid = threadIdx.x;
    const int ty = tid >> 4, tx = tid & 15;
    const int tok0 = blockIdx.x * 128;

    float acc[8][4];
#pragma unroll
    for (int i = 0; i < 8; i++)
#pragma unroll
        for (int j = 0; j < 4; j++) acc[i][j] = 0.f;

    for (int k0 = 0; k0 < HH; k0 += 32) {
        // load hidden tile (coalesced float4)
#pragma unroll
        for (int i = 0; i < 4; i++) {
            int idx = tid + i*256;          // 0..1023
            int r = idx >> 3, c4 = idx & 7; // row, float4-col
            const float4 v = *reinterpret_cast<const float4*>(
                hidden + (size_t)(tok0 + r)*HH + k0 + c4*4);
            *reinterpret_cast<float4*>(&Hs[r*36 + c4*4]) = v;
        }
        // load W tile (tag cols 0..16, pos cols 17..61, 62/63 zero)
        for (int idx = tid; idx < 32*64; idx += 256) {
            int kk = idx >> 6, c = idx & 63;
            float v = 0.f;
            if (c < TTAG)      v = Wt[(k0+kk)*TTAG + c];
            else if (c < 62)   v = Wp[(k0+kk)*TPOS + (c - TTAG)];
            Ws[idx] = v;
        }
        __syncthreads();
#pragma unroll
        for (int kk = 0; kk < 32; kk++) {
            float4 bv = *reinterpret_cast<float4*>(&Ws[kk*64 + tx*4]);
            float bx0 = bv.x, bx1 = bv.y, bx2 = bv.z, bx3 = bv.w;
#pragma unroll
            for (int i = 0; i < 8; i++) {
                float a = Hs[(ty*8+i)*36 + kk];
                acc[i][0] = fmaf(a, bx0, acc[i][0]);
                acc[i][1] = fmaf(a, bx1, acc[i][1]);
                acc[i][2] = fmaf(a, bx2, acc[i][2]);
                acc[i][3] = fmaf(a, bx3, acc[i][3]);
            }
        }
        __syncthreads();
    }
#pragma unroll
    for (int i = 0; i < 8; i++) {
        int r = tok0 + ty*8 + i;
#pragma unroll
        for (int j = 0; j < 4; j++) {
            int c = tx*4 + j;
            if (c < TTAG)
                g_tag[(size_t)r*TTAG + c] = acc[i][j] + bt[c];
            else if (c < 62)
                g_pos[(size_t)r*TPOS + (c - TTAG)] = acc[i][j] + bp[c - TTAG];
        }
    }
}

// ============================================================
// CRF: one block per (head, batch) chain. 128 threads:
//   tid in [0,T)      : NLL forward lane j=tid
//   tid in [64,64+T)  : Viterbi lane j=tid-64 (also loads emission row)
//   tid == 127        : target-path numerator accumulator
// ============================================================
__global__ __launch_bounds__(128) void crf_kernel(
    const float* __restrict__ st_t, const float* __restrict__ tr_t, const float* __restrict__ en_t,
    const float* __restrict__ st_p, const float* __restrict__ tr_p, const float* __restrict__ en_p,
    const int* __restrict__ tgt_t, const int* __restrict__ tgt_p,
    const int* __restrict__ mask,
    float* __restrict__ pred_out)
{
    __shared__ float trans_s[MAXT*MAXT];
    __shared__ float texp[MAXT*MAXT];
    __shared__ float sn[MAXT], sv[MAXT], Pw[MAXT], e_s[MAXT];
    __shared__ unsigned char hist[(SS-1)*MAXT];
    __shared__ int sh_mt;
    __shared__ float num_sh, den_sh;

    const int head = blockIdx.x >> 6;      // 0=tag, 1=pos
    const int b    = blockIdx.x & 63;
    const int T    = head ? TPOS : TTAG;
    const float* logits      = head ? g_pos : g_tag;
    const float* startv      = head ? st_p : st_t;
    const float* transg      = head ? tr_p : tr_t;
    const float* endv        = head ? en_p : en_t;
    const int* tgt           = head ? tgt_p : tgt_t;
    const float* eb = logits + (size_t)b * SS * T;
    const int tid = threadIdx.x;

    for (int idx = tid; idx < T*T; idx += 128) {
        float v = transg[idx];
        trans_s[idx] = v;
        texp[idx] = __expf(v);
    }
    if (tid < T) e_s[tid] = eb[tid];
    __syncthreads();
    if (tid < T) sn[tid] = startv[tid] + e_s[tid];
    if (tid >= 64 && tid < 64 + T) { int j = tid - 64; sv[j] = startv[j] + e_s[j]; }
    float num = 0.f; int prev = 0;
    if (tid == 127) {
        prev = tgt[b*SS];
        num = startv[prev] + e_s[prev];
    }

    for (int t = 1; t < SS; t++) {
        __syncthreads();   // phase A start: prev phase-B writes visible
        float m = -1e30f, p = 0.f;
        float best = -1e30f; int arg = 0; float ev = 0.f;
        int mt_r = 0, tg_r = 0;
        if (tid < T) {
            for (int i = 0; i < T; i++) m = fmaxf(m, sn[i]);
            p = __expf(sn[tid] - m);
        } else if (tid >= 64 && tid < 64 + T) {
            int j = tid - 64;
            ev = eb[(size_t)t*T + j];            // issue early (L2)
            for (int i = 0; i < T; i++) {
                float c = sv[i] + trans_s[i*T + j];
                if (c > best) { best = c; arg = i; }  // lowest index on ties
            }
        }
        if (tid == 127) {
            mt_r = mask[b*SS + t];
            tg_r = tgt[b*SS + t];
            sh_mt = mt_r;
        }
        if (tid < T) Pw[tid] = p;
        if (tid >= 64 && tid < 64 + T) e_s[tid - 64] = ev;
        __syncthreads();   // phase B: Pw, e_s, sh_mt ready
        if (tid < T) {
            if (sh_mt > 0) {
                float dot = 0.f;
                for (int i = 0; i < T; i++)
                    dot = fmaf(Pw[i], texp[i*T + tid], dot);
                sn[tid] = m + e_s[tid] + __logf(dot);
            }
        } else if (tid >= 64 && tid < 64 + T) {
            int j = tid - 64;
            if (sh_mt > 0) {
                sv[j] = best + e_s[j];
                hist[(t-1)*T + j] = (unsigned char)arg;
            } else {
                hist[(t-1)*T + j] = (unsigned char)j;
            }
        }
        if (tid == 127 && mt_r > 0) {
            num += trans_s[prev*T + tg_r] + e_s[tg_r];
            prev = tg_r;
        }
    }
    __syncthreads();

    if (tid == 0) {
        float m = -1e30f;
        for (int i = 0; i < T; i++) m = fmaxf(m, sn[i] + endv[i]);
        float s = 0.f;
        for (int i = 0; i < T; i++) s += __expf(sn[i] + endv[i] - m);
        den_sh = m + __logf(s);
    }
    if (tid == 127) num_sh = num + endv[prev];
    __syncthreads();
    if (tid == 0) g_diff[head*BB + b] = num_sh - den_sh;

    if (tid == 64) {  // Viterbi backtrace from shared-memory history
        float bvv = -1e30f; int cur = 0;
        for (int j = 0; j < T; j++) {
            float c = sv[j] + endv[j];
            if (c > bvv) { bvv = c; cur = j; }
        }
        float* pb = pred_out + (size_t)head*MM + (size_t)b*SS;
        pb[SS-1] = (float)cur;
        for (int tt = SS-1; tt >= 1; tt--) {
            cur = hist[(tt-1)*T + cur];
            pb[tt-1] = (float)cur;
        }
    }
}

// ============================================================
// finalize: loss = -mean(num - den) per head
// ============================================================
__global__ void finalize_kernel(float* __restrict__ out, int out_size)
{
    if (threadIdx.x == 0) {
        float s0 = 0.f, s1 = 0.f;
        for (int i = 0; i < BB; i++) { s0 += g_diff[i]; s1 += g_diff[BB + i]; }
        if (out_size > 2*MM)     out[2*MM]     = -s0 / (float)BB;   // loss_tag
        if (out_size > 2*MM + 1) out[2*MM + 1] = -s1 / (float)BB;   // loss_pos
    }
}

extern "C" void kernel_launch(void* const* d_in, const int* in_sizes, int n_in,
                              void* d_out, int out_size)
{
    const float* hidden = (const float*)d_in[0];
    const int*   mask   = (const int*)d_in[1];
    const int*   tgt_t  = (const int*)d_in[2];
    const int*   tgt_p  = (const int*)d_in[3];
    const float* Wt     = (const float*)d_in[4];
    const float* bt     = (const float*)d_in[5];
    const float* Wp     = (const float*)d_in[6];
    const float* bp     = (const float*)d_in[7];
    const float* st_t   = (const float*)d_in[8];
    const float* tr_t   = (const float*)d_in[9];
    const float* en_t   = (const float*)d_in[10];
    const float* st_p   = (const float*)d_in[11];
    const float* tr_p   = (const float*)d_in[12];
    const float* en_p   = (const float*)d_in[13];
    float* out = (float*)d_out;

    gemm_kernel<<<MM/128, 256>>>(hidden, Wt, bt, Wp, bp);
    crf_kernel<<<2*BB, 128>>>(st_t, tr_t, en_t, st_p, tr_p, en_p,
                              tgt_t, tgt_p, mask, out);
    finalize_kernel<<<1, 32>>>(out, out_size);
}

// round 4
// speedup vs baseline: 1.0014x; 1.0014x over previous
#include <cuda_runtime.h>

#define BB 64
#define SS 512
#define HH 768
#define TTAG 17
#define TPOS 45
#define MM (BB*SS)
#define MAXT 45

// ---- scratch (no allocations allowed) ----
__device__ float g_tag[MM*TTAG];   // [B*S, 17] raw tag logits
__device__ float g_pos[MM*TPOS];   // [B*S, 45] raw pos logits
__device__ float g_diff[2*BB];     // per-(head,batch) num-den

// ============================================================
// GEMM: logits = hidden @ [W_tag | W_pos] + bias
// 128 tokens x 62 cols per block, K-chunks of 32
// ============================================================
__global__ __launch_bounds__(256) void gemm_kernel(
    const float* __restrict__ hidden,
    const float* __restrict__ Wt, const float* __restrict__ bt,
    const float* __restrict__ Wp, const float* __restrict__ bp)
{
    __shared__ float Hs[128*36];   // 128 tokens x 32 k (pad 36)
    __shared__ float Ws[32*64];    // 32 k x 62 cols (pad 64)
    const int tid = threadIdx.x;
    const int ty = tid >> 4, tx = tid & 15;
    const int tok0 = blockIdx.x * 128;

    float acc[8][4];
#pragma unroll
    for (int i = 0; i < 8; i++)
#pragma unroll
        for (int j = 0; j < 4; j++) acc[i][j] = 0.f;

    for (int k0 = 0; k0 < HH; k0 += 32) {
        // load hidden tile (coalesced float4)
#pragma unroll
        for (int i = 0; i < 4; i++) {
            int idx = tid + i*256;          // 0..1023
            int r = idx >> 3, c4 = idx & 7; // row, float4-col
            const float4 v = *reinterpret_cast<const float4*>(
                hidden + (size_t)(tok0 + r)*HH + k0 + c4*4);
            *reinterpret_cast<float4*>(&Hs[r*36 + c4*4]) = v;
        }
        // load W tile (tag cols 0..16, pos cols 17..61, 62/63 zero)
        for (int idx = tid; idx < 32*64; idx += 256) {
            int kk = idx >> 6, c = idx & 63;
            float v = 0.f;
            if (c < TTAG)      v = Wt[(k0+kk)*TTAG + c];
            else if (c < 62)   v = Wp[(k0+kk)*TPOS + (c - TTAG)];
            Ws[idx] = v;
        }
        __syncthreads();
#pragma unroll
        for (int kk = 0; kk < 32; kk++) {
            float4 bv = *reinterpret_cast<float4*>(&Ws[kk*64 + tx*4]);
            float bx0 = bv.x, bx1 = bv.y, bx2 = bv.z, bx3 = bv.w;
#pragma unroll
            for (int i = 0; i < 8; i++) {
                float a = Hs[(ty*8+i)*36 + kk];
                acc[i][0] = fmaf(a, bx0, acc[i][0]);
                acc[i][1] = fmaf(a, bx1, acc[i][1]);
                acc[i][2] = fmaf(a, bx2, acc[i][2]);
                acc[i][3] = fmaf(a, bx3, acc[i][3]);
            }
        }
        __syncthreads();
    }
#pragma unroll
    for (int i = 0; i < 8; i++) {
        int r = tok0 + ty*8 + i;
#pragma unroll
        for (int j = 0; j < 4; j++) {
            int c = tx*4 + j;
            if (c < TTAG)
                g_tag[(size_t)r*TTAG + c] = acc[i][j] + bt[c];
            else if (c < 62)
                g_pos[(size_t)r*TPOS + (c - TTAG)] = acc[i][j] + bp[c - TTAG];
        }
    }
}

// ============================================================
// CRF: one block per (head, batch) chain. 128 threads:
//   tid in [0,T)      : NLL forward lane j=tid
//   tid in [64,64+T)  : Viterbi lane j=tid-64 (also loads emission row)
//   tid == 127        : target-path numerator accumulator
// ============================================================
__global__ __launch_bounds__(128) void crf_kernel(
    const float* __restrict__ st_t, const float* __restrict__ tr_t, const float* __restrict__ en_t,
    const float* __restrict__ st_p, const float* __restrict__ tr_p, const float* __restrict__ en_p,
    const int* __restrict__ tgt_t, const int* __restrict__ tgt_p,
    const int* __restrict__ mask,
    float* __restrict__ pred_out)
{
    __shared__ float trans_s[MAXT*MAXT];
    __shared__ float texp[MAXT*MAXT];
    __shared__ float sn[MAXT], sv[MAXT], Pw[MAXT], e_s[MAXT];
    __shared__ unsigned char hist[(SS-1)*MAXT];
    __shared__ int sh_mt;
    __shared__ float num_sh, den_sh;

    const int head = blockIdx.x >> 6;      // 0=tag, 1=pos
    const int b    = blockIdx.x & 63;
    const int T    = head ? TPOS : TTAG;
    const float* logits      = head ? g_pos : g_tag;
    const float* startv      = head ? st_p : st_t;
    const float* transg      = head ? tr_p : tr_t;
    const float* endv        = head ? en_p : en_t;
    const int* tgt           = head ? tgt_p : tgt_t;
    const float* eb = logits + (size_t)b * SS * T;
    const int tid = threadIdx.x;

    for (int idx = tid; idx < T*T; idx += 128) {
        float v = transg[idx];
        trans_s[idx] = v;
        texp[idx] = __expf(v);
    }
    if (tid < T) e_s[tid] = eb[tid];
    __syncthreads();
    if (tid < T) sn[tid] = startv[tid] + e_s[tid];
    if (tid >= 64 && tid < 64 + T) { int j = tid - 64; sv[j] = startv[j] + e_s[j]; }
    float num = 0.f; int prev = 0;
    if (tid == 127) {
        prev = tgt[b*SS];
        num = startv[prev] + e_s[prev];
    }

    for (int t = 1; t < SS; t++) {
        __syncthreads();   // phase A start: prev phase-B writes visible
        float m = -1e30f, p = 0.f;
        float best = -1e30f; int arg = 0; float ev = 0.f;
        int mt_r = 0, tg_r = 0;
        if (tid < T) {
            for (int i = 0; i < T; i++) m = fmaxf(m, sn[i]);
            p = __expf(sn[tid] - m);
        } else if (tid >= 64 && tid < 64 + T) {
            int j = tid - 64;
            ev = eb[(size_t)t*T + j];            // issue early (L2)
            for (int i = 0; i < T; i++) {
                float c = sv[i] + trans_s[i*T + j];
                if (c > best) { best = c; arg = i; }  // lowest index on ties
            }
        }
        if (tid == 127) {
            mt_r = mask[b*SS + t];
            tg_r = tgt[b*SS + t];
            sh_mt = mt_r;
        }
        if (tid < T) Pw[tid] = p;
        if (tid >= 64 && tid < 64 + T) e_s[tid - 64] = ev;
        __syncthreads();   // phase B: Pw, e_s, sh_mt ready
        if (tid < T) {
            if (sh_mt > 0) {
                float dot = 0.f;
                for (int i = 0; i < T; i++)
                    dot = fmaf(Pw[i], texp[i*T + tid], dot);
                sn[tid] = m + e_s[tid] + __logf(dot);
            }
        } else if (tid >= 64 && tid < 64 + T) {
            int j = tid - 64;
            if (sh_mt > 0) {
                sv[j] = best + e_s[j];
                hist[(t-1)*T + j] = (unsigned char)arg;
            } else {
                hist[(t-1)*T + j] = (unsigned char)j;
            }
        }
        if (tid == 127 && mt_r > 0) {
            num += trans_s[prev*T + tg_r] + e_s[tg_r];
            prev = tg_r;
        }
    }
    __syncthreads();

    if (tid == 0) {
        float m = -1e30f;
        for (int i = 0; i < T; i++) m = fmaxf(m, sn[i] + endv[i]);
        float s = 0.f;
        for (int i = 0; i < T; i++) s += __expf(sn[i] + endv[i] - m);
        den_sh = m + __logf(s);
    }
    if (tid == 127) num_sh = num + endv[prev];
    __syncthreads();
    if (tid == 0) g_diff[head*BB + b] = num_sh - den_sh;

    if (tid == 64) {  // Viterbi backtrace from shared-memory history
        float bvv = -1e30f; int cur = 0;
        for (int j = 0; j < T; j++) {
            float c = sv[j] + endv[j];
            if (c > bvv) { bvv = c; cur = j; }
        }
        float* pb = pred_out + (size_t)head*MM + (size_t)b*SS;
        pb[SS-1] = (float)cur;
        for (int tt = SS-1; tt >= 1; tt--) {
            cur = hist[(tt-1)*T + cur];
            pb[tt-1] = (float)cur;
        }
    }
}

// ============================================================
// finalize: loss = -mean(num - den) per head
// ============================================================
__global__ void finalize_kernel(float* __restrict__ out, int out_size)
{
    if (threadIdx.x == 0) {
        float s0 = 0.f, s1 = 0.f;
        for (int i = 0; i < BB; i++) { s0 += g_diff[i]; s1 += g_diff[BB + i]; }
        if (out_size > 2*MM)     out[2*MM]     = -s0 / (float)BB;   // loss_tag
        if (out_size > 2*MM + 1) out[2*MM + 1] = -s1 / (float)BB;   // loss_pos
    }
}

extern "C" void kernel_launch(void* const* d_in, const int* in_sizes, int n_in,
                              void* d_out, int out_size)
{
    const float* hidden = (const float*)d_in[0];
    const int*   mask   = (const int*)d_in[1];
    const int*   tgt_t  = (const int*)d_in[2];
    const int*   tgt_p  = (const int*)d_in[3];
    const float* Wt     = (const float*)d_in[4];
    const float* bt     = (const float*)d_in[5];
    const float* Wp     = (const float*)d_in[6];
    const float* bp     = (const float*)d_in[7];
    const float* st_t   = (const float*)d_in[8];
    const float* tr_t   = (const float*)d_in[9];
    const float* en_t   = (const float*)d_in[10];
    const float* st_p   = (const float*)d_in[11];
    const float* tr_p   = (const float*)d_in[12];
    const float* en_p   = (const float*)d_in[13];
    float* out = (float*)d_out;

    gemm_kernel<<<MM/128, 256>>>(hidden, Wt, bt, Wp, bp);
    crf_kernel<<<2*BB, 128>>>(st_t, tr_t, en_t, st_p, tr_p, en_p,
                              tgt_t, tgt_p, mask, out);
    finalize_kernel<<<1, 32>>>(out, out_size);
}

// round 5
// speedup vs baseline: 1.4858x; 1.4838x over previous
#include <cuda_runtime.h>

#define BB 64
#define SS 512
#define HH 768
#define TTAG 17
#define TPOS 45
#define MM (BB*SS)
#define MAXT 45

// ---- scratch (no allocations allowed) ----
__device__ float g_tag[MM*TTAG];   // [B*S, 17] raw tag logits
__device__ float g_pos[MM*TPOS];   // [B*S, 45] raw pos logits
__device__ float g_diff[2*BB];     // per-(head,batch) num-den

// ============================================================
// GEMM: logits = hidden @ [W_tag | W_pos] + bias
// 128 tokens x 62 cols per block, K-chunks of 32,
// register double-buffered global loads.
// ============================================================
__global__ __launch_bounds__(256, 2) void gemm_kernel(
    const float* __restrict__ hidden,
    const float* __restrict__ Wt, const float* __restrict__ bt,
    const float* __restrict__ Wp, const float* __restrict__ bp)
{
    __shared__ float Hs[128*36];   // 128 tokens x 32 k (pad 36)
    __shared__ float Ws[32*64];    // 32 k x 62 cols (pad 64)
    const int tid = threadIdx.x;
    const int ty = tid >> 4, tx = tid & 15;
    const int tok0 = blockIdx.x * 128;

    float acc[8][4];
#pragma unroll
    for (int i = 0; i < 8; i++)
#pragma unroll
        for (int j = 0; j < 4; j++) acc[i][j] = 0.f;

    float4 hreg[4];
    float  wreg[8];

    // prologue: load chunk 0
    {
        const int k0 = 0;
#pragma unroll
        for (int i = 0; i < 4; i++) {
            int idx = tid + i*256;
            int r = idx >> 3, c4 = idx & 7;
            hreg[i] = *reinterpret_cast<const float4*>(
                hidden + (size_t)(tok0 + r)*HH + k0 + c4*4);
        }
#pragma unroll
        for (int i = 0; i < 8; i++) {
            int idx = tid + i*256;
            int kk = idx >> 6, c = idx & 63;
            float v = 0.f;
            if (c < TTAG)    v = Wt[(k0+kk)*TTAG + c];
            else if (c < 62) v = Wp[(k0+kk)*TPOS + (c - TTAG)];
            wreg[i] = v;
        }
    }

    for (int ch = 0; ch < HH/32; ch++) {
        // commit prefetched regs to smem
#pragma unroll
        for (int i = 0; i < 4; i++) {
            int idx = tid + i*256;
            int r = idx >> 3, c4 = idx & 7;
            *reinterpret_cast<float4*>(&Hs[r*36 + c4*4]) = hreg[i];
        }
#pragma unroll
        for (int i = 0; i < 8; i++) Ws[tid + i*256] = wreg[i];
        __syncthreads();

        // prefetch next chunk (in flight during compute)
        if (ch + 1 < HH/32) {
            const int k0 = (ch+1)*32;
#pragma unroll
            for (int i = 0; i < 4; i++) {
                int idx = tid + i*256;
                int r = idx >> 3, c4 = idx & 7;
                hreg[i] = *reinterpret_cast<const float4*>(
                    hidden + (size_t)(tok0 + r)*HH + k0 + c4*4);
            }
#pragma unroll
            for (int i = 0; i < 8; i++) {
                int idx = tid + i*256;
                int kk = idx >> 6, c = idx & 63;
                float v = 0.f;
                if (c < TTAG)    v = Wt[(k0+kk)*TTAG + c];
                else if (c < 62) v = Wp[(k0+kk)*TPOS + (c - TTAG)];
                wreg[i] = v;
            }
        }

#pragma unroll
        for (int kk = 0; kk < 32; kk++) {
            float4 bv = *reinterpret_cast<float4*>(&Ws[kk*64 + tx*4]);
#pragma unroll
            for (int i = 0; i < 8; i++) {
                float a = Hs[(ty*8+i)*36 + kk];
                acc[i][0] = fmaf(a, bv.x, acc[i][0]);
                acc[i][1] = fmaf(a, bv.y, acc[i][1]);
                acc[i][2] = fmaf(a, bv.z, acc[i][2]);
                acc[i][3] = fmaf(a, bv.w, acc[i][3]);
            }
        }
        __syncthreads();
    }
#pragma unroll
    for (int i = 0; i < 8; i++) {
        int r = tok0 + ty*8 + i;
#pragma unroll
        for (int j = 0; j < 4; j++) {
            int c = tx*4 + j;
            if (c < TTAG)
                g_tag[(size_t)r*TTAG + c] = acc[i][j] + bt[c];
            else if (c < 62)
                g_pos[(size_t)r*TPOS + (c - TTAG)] = acc[i][j] + bp[c - TTAG];
        }
    }
}

// ============================================================
// CRF: one block per (head, batch) chain.
// Scaled-linear-space forward (no per-step max/log), register-cached
// transition columns, double-buffered state, ONE barrier per step.
//   tid in [0,T)      : forward lane j
//   tid in [64,64+T)  : Viterbi lane j (also prefetches emissions)
//   tid == 127        : numerator + normalizer bookkeeping
// ============================================================
struct CrfSmem {
    float trans[MAXT*MAXT];
    float st[MAXT], en[MAXT];
    float a[2][MAXT];      // forward vars (linear, rescaled)
    float sv[2][MAXT];     // viterbi scores
    float e[2][MAXT];      // emission double-buffer
    float invc[2];         // lagged normalizer
    short tgt_s[SS];
    int   mask_s[SS];
    unsigned char hist[(SS-1)*MAXT];
};

template<int T>
__device__ __forceinline__ void crf_chain(
    CrfSmem& s,
    const float* __restrict__ stg, const float* __restrict__ trg,
    const float* __restrict__ eng,
    const int* __restrict__ tgt, const int* __restrict__ mask,
    const float* __restrict__ eb, int b,
    float* __restrict__ pred, float* __restrict__ diff_slot)
{
    const int tid = threadIdx.x;
    constexpr int Q = (T + 3) / 4;   // viterbi chunk size

    // ---- init shared ----
    for (int i = tid; i < T*T; i += 128) s.trans[i] = trg[i];
    if (tid < T) { s.st[tid] = stg[tid]; s.en[tid] = eng[tid]; }
    for (int i = tid; i < SS; i += 128) {
        s.mask_s[i] = mask[b*SS + i];
        s.tgt_s[i]  = (short)tgt[b*SS + i];
    }
    if (tid < T) { s.e[0][tid] = eb[tid]; s.e[1][tid] = eb[T + tid]; }
    if (tid == 127) { s.invc[0] = 1.f; s.invc[1] = 1.f; }
    __syncthreads();

    // ---- register-cache transition columns ----
    float tcol[T];
    if (tid < T) {
#pragma unroll
        for (int i = 0; i < T; i++) tcol[i] = __expf(s.trans[i*T + tid]);
    } else if (tid >= 64 && tid < 64 + T) {
        int j = tid - 64;
#pragma unroll
        for (int i = 0; i < T; i++) tcol[i] = s.trans[i*T + j];
    }

    // ---- t = 0 state ----
    float ref0 = s.st[0] + s.e[0][0];
    if (tid < T) s.a[0][tid] = __expf(s.st[tid] + s.e[0][tid] - ref0);
    if (tid >= 64 && tid < 64 + T) { int j = tid - 64; s.sv[0][j] = s.st[j] + s.e[0][j]; }
    float num = 0.f, L = ref0;
    float cpriv[2] = {1.f, 1.f};
    int prev = 0;
    if (tid == 127) { prev = s.tgt_s[0]; num = s.st[prev] + s.e[0][prev]; }
    __syncthreads();

    // ---- main loop: ONE barrier per step ----
    for (int t = 1; t < SS; t++) {
        const int pb = (t-1) & 1, cb = t & 1;
        const int mt = s.mask_s[t];
        if (tid < T) {
            float d[4] = {0.f, 0.f, 0.f, 0.f};
#pragma unroll
            for (int i = 0; i < T; i++)
                d[i & 3] = fmaf(s.a[pb][i], tcol[i], d[i & 3]);
            float dot = (d[0] + d[1]) + (d[2] + d[3]);
            if (mt > 0)
                s.a[cb][tid] = dot * __expf(s.e[cb][tid] - s.e[cb][0]) * s.invc[pb];
            else
                s.a[cb][tid] = s.a[pb][tid];
        } else if (tid >= 64 && tid < 64 + T) {
            int j = tid - 64;
            float ev = (t + 1 < SS) ? eb[(size_t)(t+1)*T + j] : 0.f;  // prefetch
            float bbv[4]; int aav[4];
#pragma unroll
            for (int c = 0; c < 4; c++) { bbv[c] = -1e30f; aav[c] = 0; }
#pragma unroll
            for (int i = 0; i < T; i++) {
                int chn = i / Q;
                float c = s.sv[pb][i] + tcol[i];
                if (c > bbv[chn]) { bbv[chn] = c; aav[chn] = i; }  // first-max
            }
            float best = bbv[0]; int arg = aav[0];
#pragma unroll
            for (int c = 1; c < 4; c++)
                if (c*Q < T && bbv[c] > best) { best = bbv[c]; arg = aav[c]; }
            if (mt > 0) {
                s.sv[cb][j] = best + s.e[cb][j];
                s.hist[(t-1)*T + j] = (unsigned char)arg;
            } else {
                s.sv[cb][j] = s.sv[pb][j];
                s.hist[(t-1)*T + j] = (unsigned char)j;
            }
            if (t + 1 < SS) s.e[pb][j] = ev;   // (t+1)&1 == pb
        } else if (tid == 127) {
            float d[4] = {0.f, 0.f, 0.f, 0.f};
#pragma unroll
            for (int i = 0; i < T; i++)
                d[i & 3] += s.a[pb][i];
            float sum = (d[0] + d[1]) + (d[2] + d[3]);
            if (mt > 0) {
                int tg = s.tgt_s[t];
                num += s.trans[prev*T + tg] + s.e[cb][tg];
                prev = tg;
                L += s.e[cb][0] - __logf(cpriv[pb]);  // + log(c_used)
            }
            float ninv = 1.f / sum;
            cpriv[cb] = ninv;
            s.invc[cb] = ninv;
        }
        __syncthreads();
    }

    // ---- finals ----
    if (tid == 127) {
        float sum = 0.f;
#pragma unroll
        for (int i = 0; i < T; i++) sum += s.a[1][i] * __expf(s.en[i]);
        float den = L + __logf(sum);
        num += s.en[prev];
        *diff_slot = num - den;
    }
    if (tid == 64) {   // Viterbi backtrace (shared-mem history)
        float bvv = -1e30f; int cur = 0;
#pragma unroll
        for (int j = 0; j < T; j++) {
            float c = s.sv[1][j] + s.en[j];
            if (c > bvv) { bvv = c; cur = j; }
        }
        pred[SS-1] = (float)cur;
        for (int tt = SS-1; tt >= 1; tt--) {
            cur = s.hist[(tt-1)*T + cur];
            pred[tt-1] = (float)cur;
        }
    }
}

__global__ __launch_bounds__(128) void crf_kernel(
    const float* __restrict__ st_t, const float* __restrict__ tr_t, const float* __restrict__ en_t,
    const float* __restrict__ st_p, const float* __restrict__ tr_p, const float* __restrict__ en_p,
    const int* __restrict__ tgt_t, const int* __restrict__ tgt_p,
    const int* __restrict__ mask,
    float* __restrict__ pred_out)
{
    __shared__ CrfSmem s;
    const int head = blockIdx.x >> 6;      // 0=tag, 1=pos
    const int b    = blockIdx.x & 63;
    float* pred = pred_out + (size_t)head*MM + (size_t)b*SS;
    float* diff = &g_diff[head*BB + b];
    if (head == 0) {
        const float* eb = g_tag + (size_t)b * SS * TTAG;
        crf_chain<TTAG>(s, st_t, tr_t, en_t, tgt_t, mask, eb, b, pred, diff);
    } else {
        const float* eb = g_pos + (size_t)b * SS * TPOS;
        crf_chain<TPOS>(s, st_p, tr_p, en_p, tgt_p, mask, eb, b, pred, diff);
    }
}

// ============================================================
// finalize: loss = -mean(num - den) per head
// ============================================================
__global__ void finalize_kernel(float* __restrict__ out, int out_size)
{
    if (threadIdx.x == 0) {
        float s0 = 0.f, s1 = 0.f;
        for (int i = 0; i < BB; i++) { s0 += g_diff[i]; s1 += g_diff[BB + i]; }
        if (out_size > 2*MM)     out[2*MM]     = -s0 / (float)BB;   // loss_tag
        if (out_size > 2*MM + 1) out[2*MM + 1] = -s1 / (float)BB;   // loss_pos
    }
}

extern "C" void kernel_launch(void* const* d_in, const int* in_sizes, int n_in,
                              void* d_out, int out_size)
{
    const float* hidden = (const float*)d_in[0];
    const int*   mask   = (const int*)d_in[1];
    const int*   tgt_t  = (const int*)d_in[2];
    const int*   tgt_p  = (const int*)d_in[3];
    const float* Wt     = (const float*)d_in[4];
    const float* bt     = (const float*)d_in[5];
    const float* Wp     = (const float*)d_in[6];
    const float* bp     = (const float*)d_in[7];
    const float* st_t   = (const float*)d_in[8];
    const float* tr_t   = (const float*)d_in[9];
    const float* en_t   = (const float*)d_in[10];
    const float* st_p   = (const float*)d_in[11];
    const float* tr_p   = (const float*)d_in[12];
    const float* en_p   = (const float*)d_in[13];
    float* out = (float*)d_out;

    gemm_kernel<<<MM/128, 256>>>(hidden, Wt, bt, Wp, bp);
    crf_kernel<<<2*BB, 128>>>(st_t, tr_t, en_t, st_p, tr_p, en_p,
                              tgt_t, tgt_p, mask, out);
    finalize_kernel<<<1, 32>>>(out, out_size);
}

// round 6
// speedup vs baseline: 2.0892x; 1.4061x over previous
#include <cuda_runtime.h>

#define BB 64
#define SS 512
#define HH 768
#define TTAG 17
#define TPOS 45
#define MM (BB*SS)
#define MAXT 45

// ---- scratch (no allocations allowed) ----
__device__ float g_tag[MM*TTAG];    // raw tag logits
__device__ float g_pos[MM*TPOS];    // raw pos logits
__device__ float g_Etag[MM*TTAG];   // exp(e_j - e_0)
__device__ float g_Epos[MM*TPOS];
__device__ float g_diff[2*BB];      // per-(head,batch) num-den

// ---- packed f32x2 helpers ----
__device__ __forceinline__ void fma2(unsigned long long& d,
                                     unsigned long long a, unsigned long long b) {
    asm("fma.rn.f32x2 %0, %1, %2, %3;" : "=l"(d) : "l"(a), "l"(b), "l"(d));
}
__device__ __forceinline__ unsigned long long add2(unsigned long long a, unsigned long long b) {
    unsigned long long d;
    asm("add.rn.f32x2 %0, %1, %2;" : "=l"(d) : "l"(a), "l"(b));
    return d;
}
__device__ __forceinline__ unsigned long long pack2(float lo, float hi) {
    unsigned long long d;
    asm("mov.b64 %0, {%1, %2};" : "=l"(d)
        : "r"(__float_as_uint(lo)), "r"(__float_as_uint(hi)));
    return d;
}
__device__ __forceinline__ void unpack2(unsigned long long v, float& lo, float& hi) {
    unsigned a, b;
    asm("mov.b64 {%0, %1}, %2;" : "=r"(a), "=r"(b) : "l"(v));
    lo = __uint_as_float(a); hi = __uint_as_float(b);
}

// ============================================================
// GEMM (unchanged from R5: ~99us, near fp32 roofline)
// ============================================================
__global__ __launch_bounds__(256, 2) void gemm_kernel(
    const float* __restrict__ hidden,
    const float* __restrict__ Wt, const float* __restrict__ bt,
    const float* __restrict__ Wp, const float* __restrict__ bp)
{
    __shared__ float Hs[128*36];
    __shared__ float Ws[32*64];
    const int tid = threadIdx.x;
    const int ty = tid >> 4, tx = tid & 15;
    const int tok0 = blockIdx.x * 128;

    float acc[8][4];
#pragma unroll
    for (int i = 0; i < 8; i++)
#pragma unroll
        for (int j = 0; j < 4; j++) acc[i][j] = 0.f;

    float4 hreg[4];
    float  wreg[8];
    {
#pragma unroll
        for (int i = 0; i < 4; i++) {
            int idx = tid + i*256;
            int r = idx >> 3, c4 = idx & 7;
            hreg[i] = *reinterpret_cast<const float4*>(
                hidden + (size_t)(tok0 + r)*HH + c4*4);
        }
#pragma unroll
        for (int i = 0; i < 8; i++) {
            int idx = tid + i*256;
            int kk = idx >> 6, c = idx & 63;
            float v = 0.f;
            if (c < TTAG)    v = Wt[kk*TTAG + c];
            else if (c < 62) v = Wp[kk*TPOS + (c - TTAG)];
            wreg[i] = v;
        }
    }
    for (int ch = 0; ch < HH/32; ch++) {
#pragma unroll
        for (int i = 0; i < 4; i++) {
            int idx = tid + i*256;
            int r = idx >> 3, c4 = idx & 7;
            *reinterpret_cast<float4*>(&Hs[r*36 + c4*4]) = hreg[i];
        }
#pragma unroll
        for (int i = 0; i < 8; i++) Ws[tid + i*256] = wreg[i];
        __syncthreads();
        if (ch + 1 < HH/32) {
            const int k0 = (ch+1)*32;
#pragma unroll
            for (int i = 0; i < 4; i++) {
                int idx = tid + i*256;
                int r = idx >> 3, c4 = idx & 7;
                hreg[i] = *reinterpret_cast<const float4*>(
                    hidden + (size_t)(tok0 + r)*HH + k0 + c4*4);
            }
#pragma unroll
            for (int i = 0; i < 8; i++) {
                int idx = tid + i*256;
                int kk = idx >> 6, c = idx & 63;
                float v = 0.f;
                if (c < TTAG)    v = Wt[(k0+kk)*TTAG + c];
                else if (c < 62) v = Wp[(k0+kk)*TPOS + (c - TTAG)];
                wreg[i] = v;
            }
        }
#pragma unroll
        for (int kk = 0; kk < 32; kk++) {
            float4 bv = *reinterpret_cast<float4*>(&Ws[kk*64 + tx*4]);
#pragma unroll
            for (int i = 0; i < 8; i++) {
                float a = Hs[(ty*8+i)*36 + kk];
                acc[i][0] = fmaf(a, bv.x, acc[i][0]);
                acc[i][1] = fmaf(a, bv.y, acc[i][1]);
                acc[i][2] = fmaf(a, bv.z, acc[i][2]);
                acc[i][3] = fmaf(a, bv.w, acc[i][3]);
            }
        }
        __syncthreads();
    }
#pragma unroll
    for (int i = 0; i < 8; i++) {
        int r = tok0 + ty*8 + i;
#pragma unroll
        for (int j = 0; j < 4; j++) {
            int c = tx*4 + j;
            if (c < TTAG)
                g_tag[(size_t)r*TTAG + c] = acc[i][j] + bt[c];
            else if (c < 62)
                g_pos[(size_t)r*TPOS + (c - TTAG)] = acc[i][j] + bp[c - TTAG];
        }
    }
}

// ============================================================
// E precompute: E[t][j] = exp(e[t][j] - e[t][0])
// ============================================================
__global__ __launch_bounds__(64) void expe_kernel()
{
    const int r = blockIdx.x;       // token 0..MM-1
    const int t = threadIdx.x;      // 0..63
    __shared__ float b0[2];
    if (t == 0) b0[0] = g_tag[(size_t)r*TTAG];
    if (t == 1) b0[1] = g_pos[(size_t)r*TPOS];
    __syncthreads();
    if (t < TTAG)
        g_Etag[(size_t)r*TTAG + t] = __expf(g_tag[(size_t)r*TTAG + t] - b0[0]);
    else if (t < TTAG + TPOS) {
        int j = t - TTAG;
        g_Epos[(size_t)r*TPOS + j] = __expf(g_pos[(size_t)r*TPOS + j] - b0[1]);
    }
}

// ============================================================
// CRF: one block per (head,batch) chain. 160 threads:
//   warp 0: forward recurrence (scaled-linear, FFMA2 packed)
//   warps 1-3: Viterbi (2 lanes per column, shfl combine)
//   warp 4: normalizer bookkeeping + numerator epilogue
// named bars: id1 = {w0,w4} (64), id2 = {w1,w2,w3} (96)
// ============================================================
struct __align__(16) CrfSmem {
    float a2[2][96];       // duplicated pairs (a_i,a_i), 2*T used
    float sv[2][48];       // viterbi scores
    float invc[2];
    unsigned mword[16];    // packed mask bits
    unsigned char hist[(SS-1)*MAXT];
    unsigned char path[SS];
};

template<int T>
__device__ __forceinline__ void crf_chain(
    CrfSmem& s,
    const float* __restrict__ stg, const float* __restrict__ trg,
    const float* __restrict__ eng,
    const int* __restrict__ tgt, const int* __restrict__ mask,
    const float* __restrict__ eb, const float* __restrict__ Eb, int b,
    float* __restrict__ pred, float* __restrict__ diff_slot)
{
    const int tid = threadIdx.x;
    const int w = tid >> 5, lane = tid & 31;
    constexpr int SHC = (T + 1) / 2;            // forward cols per lane split
    constexpr int BASE_B = (T/2) & ~3;          // viterbi B-half start (16B aligned)
    constexpr int CA = T - BASE_B;              // viterbi scan count (both halves)

    // ---- init ----
    if (tid < 16) {
        unsigned bits = 0;
#pragma unroll
        for (int k = 0; k < 32; k++)
            bits |= (mask[b*SS + tid*32 + k] != 0 ? 1u : 0u) << k;
        s.mword[tid] = bits;
    }
    if (tid == 0) { s.invc[0] = 1.f; s.invc[1] = 1.f; }

    if (w == 0 && lane < SHC) {
        int j0 = lane, j1 = (lane + SHC < T) ? lane + SHC : lane;
        float r0 = stg[0] + eb[0];
        float a0 = __expf(stg[j0] + eb[j0] - r0);
        float a1 = __expf(stg[j1] + eb[j1] - r0);
        *(unsigned long long*)&s.a2[0][2*j0] = pack2(a0, a0);
        *(unsigned long long*)&s.a2[0][2*j1] = pack2(a1, a1);
    }
    if (w >= 1 && w <= 3) {
        int vl = tid - 32, col = vl >> 1;
        if (col < T && !(vl & 1)) s.sv[0][col] = stg[col] + eb[col];
    }
    __syncthreads();

    if (w == 0) {
        // ================= forward warp =================
        const bool act = lane < SHC;
        const int j0 = act ? lane : 0;
        const int j1 = (act && lane + SHC < T) ? lane + SHC : j0;
        unsigned long long tc2[T];
#pragma unroll
        for (int i = 0; i < T; i++)
            tc2[i] = pack2(__expf(trg[i*T + j0]), __expf(trg[i*T + j1]));
        float r0 = stg[0] + eb[0];
        float acur0 = __expf(stg[j0] + eb[j0] - r0);
        float acur1 = __expf(stg[j1] + eb[j1] - r0);
        float E0n = Eb[T + j0], E1n = Eb[T + j1];

        for (int t = 1; t < SS; t++) {
            const int pb = (t-1) & 1, cb = t & 1;
            float iv = s.invc[pb];
            unsigned mt = (s.mword[t >> 5] >> (t & 31)) & 1u;
            float E0 = E0n, E1 = E1n;
            if (t + 1 < SS) { E0n = Eb[(t+1)*T + j0]; E1n = Eb[(t+1)*T + j1]; }

            unsigned long long d[4] = {0ull, 0ull, 0ull, 0ull};
            const float* ap = s.a2[pb];
#pragma unroll
            for (int k = 0; k < T/2; k++) {
                ulonglong2 q = *(const ulonglong2*)(ap + 4*k);
                fma2(d[(2*k) & 3],   q.x, tc2[2*k]);
                fma2(d[(2*k+1) & 3], q.y, tc2[2*k+1]);
            }
            if (T & 1) {
                unsigned long long qa = *(const unsigned long long*)(ap + 2*(T-1));
                fma2(d[(T-1) & 3], qa, tc2[T-1]);
            }
            unsigned long long dd = add2(add2(d[0], d[1]), add2(d[2], d[3]));
            float dot0, dot1; unpack2(dd, dot0, dot1);
            float v0 = mt ? dot0 * iv * E0 : acur0;
            float v1 = mt ? dot1 * iv * E1 : acur1;
            acur0 = v0; acur1 = v1;
            if (act) {
                *(unsigned long long*)&s.a2[cb][2*j0] = pack2(v0, v0);
                *(unsigned long long*)&s.a2[cb][2*j1] = pack2(v1, v1);
            }
            asm volatile("bar.sync 1, 64;" ::: "memory");
        }
    } else if (w == 4) {
        // ================= bookkeeping warp =================
        float cpA = 1.f, cpB = 1.f, L = 0.f;
        float e0n = 0.f;
        if (lane == 0) { L = stg[0] + eb[0]; e0n = eb[T]; }
        for (int t = 1; t < SS; t++) {
            const int pb = (t-1) & 1, cb = t & 1;
            if (lane == 0) {
                unsigned mt = (s.mword[t >> 5] >> (t & 31)) & 1u;
                float e0t = e0n;
                if (t + 1 < SS) e0n = eb[(t+1)*T];
                float sm0 = 0.f, sm1 = 0.f, sm2 = 0.f, sm3 = 0.f;
                const float* ap = s.a2[pb];
#pragma unroll
                for (int i = 0; i < T; i++) {
                    float v = ap[2*i];
                    if ((i & 3) == 0) sm0 += v;
                    else if ((i & 3) == 1) sm1 += v;
                    else if ((i & 3) == 2) sm2 += v;
                    else sm3 += v;
                }
                float sum = (sm0 + sm1) + (sm2 + sm3);
                float cp = pb ? cpB : cpA;
                if (mt) L += e0t - __logf(cp);
                float ninv = 1.f / sum;
                if (cb) cpB = ninv; else cpA = ninv;
                s.invc[cb] = ninv;
            }
            asm volatile("bar.sync 1, 64;" ::: "memory");
        }
        // numerator (parallel over t, epilogue)
        float pacc = 0.f; int mxt = 0;
        for (int t = lane; t < SS; t += 32) {
            int tg = tgt[b*SS + t];
            if (t == 0) {
                pacc += stg[tg] + eb[tg];
            } else if (mask[b*SS + t] > 0) {
                int tgp = tgt[b*SS + t - 1];
                pacc += trg[tgp*T + tg] + eb[(size_t)t*T + tg];
                mxt = max(mxt, t);
            }
        }
#pragma unroll
        for (int o = 16; o > 0; o >>= 1) {
            pacc += __shfl_xor_sync(0xffffffffu, pacc, o);
            mxt = max(mxt, __shfl_xor_sync(0xffffffffu, mxt, o));
        }
        if (lane == 0) {
            int last = tgt[b*SS + mxt];
            float num = pacc + eng[last];
            float sm = 0.f;
#pragma unroll
            for (int i = 0; i < T; i++) sm += s.a2[1][2*i] * __expf(eng[i]);
            float den = L + __logf(sm);
            *diff_slot = num - den;
        }
    } else {
        // ================= viterbi warps (1-3) =================
        const int vl = tid - 32;
        const int col = vl >> 1;
        const bool act = col < T;
        const bool isA = !(vl & 1);
        const int jj = act ? col : 0;
        const int base = isA ? 0 : BASE_B;
        float tc[CA];
#pragma unroll
        for (int k = 0; k < CA; k++) tc[k] = trg[(base + k)*T + jj];
        float svprev = stg[jj] + eb[jj];
        float evcur = eb[T + jj];   // e[1][jj]

        for (int t = 1; t < SS; t++) {
            const int pb = (t-1) & 1, cb = t & 1;
            float evn = (t + 1 < SS) ? eb[(size_t)(t+1)*T + jj] : 0.f;
            // load my half of sv[pb]
            float svv[CA];
            const float* sp = s.sv[pb] + base;
            constexpr int C4 = CA / 4;
#pragma unroll
            for (int k = 0; k < C4; k++) {
                float4 q = *(const float4*)(sp + 4*k);
                svv[4*k+0] = q.x; svv[4*k+1] = q.y;
                svv[4*k+2] = q.z; svv[4*k+3] = q.w;
            }
#pragma unroll
            for (int r = 4*C4; r < CA; r++) svv[r] = sp[r];
            // chunked first-argmax (contiguous chunks keep lowest-index ties)
            constexpr int NCH = (CA + 6) / 7;
            float bb[NCH]; int aa[NCH];
#pragma unroll
            for (int c = 0; c < NCH; c++) { bb[c] = -1e30f; aa[c] = 0; }
#pragma unroll
            for (int k = 0; k < CA; k++) {
                float cd = svv[k] + tc[k];
                int c = k / 7;
                if (cd > bb[c]) { bb[c] = cd; aa[c] = base + k; }
            }
            float best = bb[0]; int arg = aa[0];
#pragma unroll
            for (int c = 1; c < NCH; c++)
                if (bb[c] > best) { best = bb[c]; arg = aa[c]; }
            // exchange with partner lane (A holds prefix -> wins ties)
            float bo = __shfl_xor_sync(0xffffffffu, best, 1);
            int   ao = __shfl_xor_sync(0xffffffffu, arg, 1);
            if (isA && act) {
                if (bo > best) { best = bo; arg = ao; }
                unsigned mt = (s.mword[t >> 5] >> (t & 31)) & 1u;
                float e = evcur;
                float svnew; unsigned char h;
                if (mt) { svnew = best + e; h = (unsigned char)arg; }
                else    { svnew = svprev;   h = (unsigned char)col; }
                s.sv[cb][col] = svnew;
                svprev = svnew;
                s.hist[(t-1)*T + col] = h;
            }
            evcur = evn;
            asm volatile("bar.sync 2, 96;" ::: "memory");
        }
        // backtrace (warp 1, lane 0), then coalesced write by warp 1
        if (tid == 32) {
            float bv = -1e30f; int cur = 0;
#pragma unroll
            for (int j = 0; j < T; j++) {
                float c = s.sv[1][j] + eng[j];
                if (c > bv) { bv = c; cur = j; }
            }
            s.path[SS-1] = (unsigned char)cur;
            for (int tt = SS-1; tt >= 1; tt--) {
                cur = s.hist[(tt-1)*T + cur];
                s.path[tt-1] = (unsigned char)cur;
            }
        }
        if (w == 1) {
            __syncwarp();
            for (int i = lane; i < SS; i += 32) pred[i] = (float)s.path[i];
        }
    }
}

__global__ __launch_bounds__(160) void crf_kernel(
    const float* __restrict__ st_t, const float* __restrict__ tr_t, const float* __restrict__ en_t,
    const float* __restrict__ st_p, const float* __restrict__ tr_p, const float* __restrict__ en_p,
    const int* __restrict__ tgt_t, const int* __restrict__ tgt_p,
    const int* __restrict__ mask,
    float* __restrict__ pred_out)
{
    __shared__ CrfSmem s;
    const int head = blockIdx.x >> 6;
    const int b    = blockIdx.x & 63;
    float* pred = pred_out + (size_t)head*MM + (size_t)b*SS;
    float* diff = &g_diff[head*BB + b];
    if (head == 0)
        crf_chain<TTAG>(s, st_t, tr_t, en_t, tgt_t, mask,
                        g_tag  + (size_t)b*SS*TTAG,
                        g_Etag + (size_t)b*SS*TTAG, b, pred, diff);
    else
        crf_chain<TPOS>(s, st_p, tr_p, en_p, tgt_p, mask,
                        g_pos  + (size_t)b*SS*TPOS,
                        g_Epos + (size_t)b*SS*TPOS, b, pred, diff);
}

// ============================================================
// finalize: loss = -mean(num - den) per head
// ============================================================
__global__ void finalize_kernel(float* __restrict__ out, int out_size)
{
    if (threadIdx.x == 0) {
        float s0 = 0.f, s1 = 0.f;
        for (int i = 0; i < BB; i++) { s0 += g_diff[i]; s1 += g_diff[BB + i]; }
        if (out_size > 2*MM)     out[2*MM]     = -s0 / (float)BB;
        if (out_size > 2*MM + 1) out[2*MM + 1] = -s1 / (float)BB;
    }
}

extern "C" void kernel_launch(void* const* d_in, const int* in_sizes, int n_in,
                              void* d_out, int out_size)
{
    const float* hidden = (const float*)d_in[0];
    const int*   mask   = (const int*)d_in[1];
    const int*   tgt_t  = (const int*)d_in[2];
    const int*   tgt_p  = (const int*)d_in[3];
    const float* Wt     = (const float*)d_in[4];
    const float* bt     = (const float*)d_in[5];
    const float* Wp     = (const float*)d_in[6];
    const float* bp     = (const float*)d_in[7];
    const float* st_t   = (const float*)d_in[8];
    const float* tr_t   = (const float*)d_in[9];
    const float* en_t   = (const float*)d_in[10];
    const float* st_p   = (const float*)d_in[11];
    const float* tr_p   = (const float*)d_in[12];
    const float* en_p   = (const float*)d_in[13];
    float* out = (float*)d_out;

    gemm_kernel<<<MM/128, 256>>>(hidden, Wt, bt, Wp, bp);
    expe_kernel<<<MM, 64>>>();
    crf_kernel<<<2*BB, 160>>>(st_t, tr_t, en_t, st_p, tr_p, en_p,
                              tgt_t, tgt_p, mask, out);
    finalize_kernel<<<1, 32>>>(out, out_size);
}

// round 7
// speedup vs baseline: 2.0976x; 1.0040x over previous
#include <cuda_runtime.h>

#define BB 64
#define SS 512
#define HH 768
#define TTAG 17
#define TPOS 45
#define MM (BB*SS)
#define MAXT 45

// ---- scratch (no allocations allowed) ----
__device__ float g_tag[MM*TTAG];    // raw tag logits
__device__ float g_pos[MM*TPOS];    // raw pos logits
__device__ float g_Etag[MM*TTAG];   // exp(e_j - e_0)
__device__ float g_Epos[MM*TPOS];
__device__ float g_diff[2*BB];      // per-(head,batch) num-den

// ---- packed f32x2 helpers ----
__device__ __forceinline__ void fma2(unsigned long long& d,
                                     unsigned long long a, unsigned long long b) {
    asm("fma.rn.f32x2 %0, %1, %2, %3;" : "=l"(d) : "l"(a), "l"(b), "l"(d));
}
__device__ __forceinline__ unsigned long long add2(unsigned long long a, unsigned long long b) {
    unsigned long long d;
    asm("add.rn.f32x2 %0, %1, %2;" : "=l"(d) : "l"(a), "l"(b));
    return d;
}
__device__ __forceinline__ unsigned long long pack2(float lo, float hi) {
    unsigned long long d;
    asm("mov.b64 %0, {%1, %2};" : "=l"(d)
        : "r"(__float_as_uint(lo)), "r"(__float_as_uint(hi)));
    return d;
}
__device__ __forceinline__ void unpack2(unsigned long long v, float& lo, float& hi) {
    unsigned a, b;
    asm("mov.b64 {%0, %1}, %2;" : "=r"(a), "=r"(b) : "l"(v));
    lo = __uint_as_float(a); hi = __uint_as_float(b);
}

// ============================================================
// GEMM (unchanged from R5: ~99us, near fp32 roofline)
// ============================================================
__global__ __launch_bounds__(256, 2) void gemm_kernel(
    const float* __restrict__ hidden,
    const float* __restrict__ Wt, const float* __restrict__ bt,
    const float* __restrict__ Wp, const float* __restrict__ bp)
{
    __shared__ float Hs[128*36];
    __shared__ float Ws[32*64];
    const int tid = threadIdx.x;
    const int ty = tid >> 4, tx = tid & 15;
    const int tok0 = blockIdx.x * 128;

    float acc[8][4];
#pragma unroll
    for (int i = 0; i < 8; i++)
#pragma unroll
        for (int j = 0; j < 4; j++) acc[i][j] = 0.f;

    float4 hreg[4];
    float  wreg[8];
    {
#pragma unroll
        for (int i = 0; i < 4; i++) {
            int idx = tid + i*256;
            int r = idx >> 3, c4 = idx & 7;
            hreg[i] = *reinterpret_cast<const float4*>(
                hidden + (size_t)(tok0 + r)*HH + c4*4);
        }
#pragma unroll
        for (int i = 0; i < 8; i++) {
            int idx = tid + i*256;
            int kk = idx >> 6, c = idx & 63;
            float v = 0.f;
            if (c < TTAG)    v = Wt[kk*TTAG + c];
            else if (c < 62) v = Wp[kk*TPOS + (c - TTAG)];
            wreg[i] = v;
        }
    }
    for (int ch = 0; ch < HH/32; ch++) {
#pragma unroll
        for (int i = 0; i < 4; i++) {
            int idx = tid + i*256;
            int r = idx >> 3, c4 = idx & 7;
            *reinterpret_cast<float4*>(&Hs[r*36 + c4*4]) = hreg[i];
        }
#pragma unroll
        for (int i = 0; i < 8; i++) Ws[tid + i*256] = wreg[i];
        __syncthreads();
        if (ch + 1 < HH/32) {
            const int k0 = (ch+1)*32;
#pragma unroll
            for (int i = 0; i < 4; i++) {
                int idx = tid + i*256;
                int r = idx >> 3, c4 = idx & 7;
                hreg[i] = *reinterpret_cast<const float4*>(
                    hidden + (size_t)(tok0 + r)*HH + k0 + c4*4);
            }
#pragma unroll
            for (int i = 0; i < 8; i++) {
                int idx = tid + i*256;
                int kk = idx >> 6, c = idx & 63;
                float v = 0.f;
                if (c < TTAG)    v = Wt[(k0+kk)*TTAG + c];
                else if (c < 62) v = Wp[(k0+kk)*TPOS + (c - TTAG)];
                wreg[i] = v;
            }
        }
#pragma unroll
        for (int kk = 0; kk < 32; kk++) {
            float4 bv = *reinterpret_cast<float4*>(&Ws[kk*64 + tx*4]);
#pragma unroll
            for (int i = 0; i < 8; i++) {
                float a = Hs[(ty*8+i)*36 + kk];
                acc[i][0] = fmaf(a, bv.x, acc[i][0]);
                acc[i][1] = fmaf(a, bv.y, acc[i][1]);
                acc[i][2] = fmaf(a, bv.z, acc[i][2]);
                acc[i][3] = fmaf(a, bv.w, acc[i][3]);
            }
        }
        __syncthreads();
    }
#pragma unroll
    for (int i = 0; i < 8; i++) {
        int r = tok0 + ty*8 + i;
#pragma unroll
        for (int j = 0; j < 4; j++) {
            int c = tx*4 + j;
            if (c < TTAG)
                g_tag[(size_t)r*TTAG + c] = acc[i][j] + bt[c];
            else if (c < 62)
                g_pos[(size_t)r*TPOS + (c - TTAG)] = acc[i][j] + bp[c - TTAG];
        }
    }
}

// ============================================================
// E precompute: E[t][j] = exp(e[t][j] - e[t][0])
// ============================================================
__global__ __launch_bounds__(64) void expe_kernel()
{
    const int r = blockIdx.x;       // token 0..MM-1
    const int t = threadIdx.x;      // 0..63
    __shared__ float b0[2];
    if (t == 0) b0[0] = g_tag[(size_t)r*TTAG];
    if (t == 1) b0[1] = g_pos[(size_t)r*TPOS];
    __syncthreads();
    if (t < TTAG)
        g_Etag[(size_t)r*TTAG + t] = __expf(g_tag[(size_t)r*TTAG + t] - b0[0]);
    else if (t < TTAG + TPOS) {
        int j = t - TTAG;
        g_Epos[(size_t)r*TPOS + j] = __expf(g_pos[(size_t)r*TPOS + j] - b0[1]);
    }
}

// ============================================================
// CRF: one block per (head,batch) chain. 160 threads:
//   warp 0: forward recurrence (scaled-linear, FFMA2 packed)
//   warps 1-3: Viterbi (2 lanes per column, shfl combine)
//   warp 4: normalizer bookkeeping + numerator epilogue
// named bars: id1 = {w0,w4} (64), id2 = {w1,w2,w3} (96)
// ============================================================
struct __align__(16) CrfSmem {
    float a2[2][96];       // duplicated pairs (a_i,a_i), 2*T used
    float sv[2][48];       // viterbi scores
    float invc[2];
    unsigned mword[16];    // packed mask bits
    unsigned char hist[(SS-1)*MAXT];
    unsigned char path[SS];
};

template<int T>
__device__ __forceinline__ void crf_chain(
    CrfSmem& s,
    const float* __restrict__ stg, const float* __restrict__ trg,
    const float* __restrict__ eng,
    const int* __restrict__ tgt, const int* __restrict__ mask,
    const float* __restrict__ eb, const float* __restrict__ Eb, int b,
    float* __restrict__ pred, float* __restrict__ diff_slot)
{
    const int tid = threadIdx.x;
    const int w = tid >> 5, lane = tid & 31;
    constexpr int SHC = (T + 1) / 2;            // forward cols per lane split
    constexpr int BASE_B = (T/2) & ~3;          // viterbi B-half start (16B aligned)
    constexpr int CA = T - BASE_B;              // viterbi scan count (both halves)

    // ---- init ----
    if (tid < 16) {
        unsigned bits = 0;
#pragma unroll
        for (int k = 0; k < 32; k++)
            bits |= (mask[b*SS + tid*32 + k] != 0 ? 1u : 0u) << k;
        s.mword[tid] = bits;
    }
    if (tid == 0) { s.invc[0] = 1.f; s.invc[1] = 1.f; }

    if (w == 0 && lane < SHC) {
        int j0 = lane, j1 = (lane + SHC < T) ? lane + SHC : lane;
        float r0 = stg[0] + eb[0];
        float a0 = __expf(stg[j0] + eb[j0] - r0);
        float a1 = __expf(stg[j1] + eb[j1] - r0);
        *(unsigned long long*)&s.a2[0][2*j0] = pack2(a0, a0);
        *(unsigned long long*)&s.a2[0][2*j1] = pack2(a1, a1);
    }
    if (w >= 1 && w <= 3) {
        int vl = tid - 32, col = vl >> 1;
        if (col < T && !(vl & 1)) s.sv[0][col] = stg[col] + eb[col];
    }
    __syncthreads();

    if (w == 0) {
        // ================= forward warp =================
        const bool act = lane < SHC;
        const int j0 = act ? lane : 0;
        const int j1 = (act && lane + SHC < T) ? lane + SHC : j0;
        unsigned long long tc2[T];
#pragma unroll
        for (int i = 0; i < T; i++)
            tc2[i] = pack2(__expf(trg[i*T + j0]), __expf(trg[i*T + j1]));
        float r0 = stg[0] + eb[0];
        float acur0 = __expf(stg[j0] + eb[j0] - r0);
        float acur1 = __expf(stg[j1] + eb[j1] - r0);
        float E0n = Eb[T + j0], E1n = Eb[T + j1];

        for (int t = 1; t < SS; t++) {
            const int pb = (t-1) & 1, cb = t & 1;
            float iv = s.invc[pb];
            unsigned mt = (s.mword[t >> 5] >> (t & 31)) & 1u;
            float E0 = E0n, E1 = E1n;
            if (t + 1 < SS) { E0n = Eb[(t+1)*T + j0]; E1n = Eb[(t+1)*T + j1]; }

            unsigned long long d[4] = {0ull, 0ull, 0ull, 0ull};
            const float* ap = s.a2[pb];
#pragma unroll
            for (int k = 0; k < T/2; k++) {
                ulonglong2 q = *(const ulonglong2*)(ap + 4*k);
                fma2(d[(2*k) & 3],   q.x, tc2[2*k]);
                fma2(d[(2*k+1) & 3], q.y, tc2[2*k+1]);
            }
            if (T & 1) {
                unsigned long long qa = *(const unsigned long long*)(ap + 2*(T-1));
                fma2(d[(T-1) & 3], qa, tc2[T-1]);
            }
            unsigned long long dd = add2(add2(d[0], d[1]), add2(d[2], d[3]));
            float dot0, dot1; unpack2(dd, dot0, dot1);
            float v0 = mt ? dot0 * iv * E0 : acur0;
            float v1 = mt ? dot1 * iv * E1 : acur1;
            acur0 = v0; acur1 = v1;
            if (act) {
                *(unsigned long long*)&s.a2[cb][2*j0] = pack2(v0, v0);
                *(unsigned long long*)&s.a2[cb][2*j1] = pack2(v1, v1);
            }
            asm volatile("bar.sync 1, 64;" ::: "memory");
        }
    } else if (w == 4) {
        // ================= bookkeeping warp =================
        float cpA = 1.f, cpB = 1.f, L = 0.f;
        float e0n = 0.f;
        if (lane == 0) { L = stg[0] + eb[0]; e0n = eb[T]; }
        for (int t = 1; t < SS; t++) {
            const int pb = (t-1) & 1, cb = t & 1;
            if (lane == 0) {
                unsigned mt = (s.mword[t >> 5] >> (t & 31)) & 1u;
                float e0t = e0n;
                if (t + 1 < SS) e0n = eb[(t+1)*T];
                float sm0 = 0.f, sm1 = 0.f, sm2 = 0.f, sm3 = 0.f;
                const float* ap = s.a2[pb];
#pragma unroll
                for (int i = 0; i < T; i++) {
                    float v = ap[2*i];
                    if ((i & 3) == 0) sm0 += v;
                    else if ((i & 3) == 1) sm1 += v;
                    else if ((i & 3) == 2) sm2 += v;
                    else sm3 += v;
                }
                float sum = (sm0 + sm1) + (sm2 + sm3);
                float cp = pb ? cpB : cpA;
                if (mt) L += e0t - __logf(cp);
                float ninv = 1.f / sum;
                if (cb) cpB = ninv; else cpA = ninv;
                s.invc[cb] = ninv;
            }
            asm volatile("bar.sync 1, 64;" ::: "memory");
        }
        // numerator (parallel over t, epilogue)
        float pacc = 0.f; int mxt = 0;
        for (int t = lane; t < SS; t += 32) {
            int tg = tgt[b*SS + t];
            if (t == 0) {
                pacc += stg[tg] + eb[tg];
            } else if (mask[b*SS + t] > 0) {
                int tgp = tgt[b*SS + t - 1];
                pacc += trg[tgp*T + tg] + eb[(size_t)t*T + tg];
                mxt = max(mxt, t);
            }
        }
#pragma unroll
        for (int o = 16; o > 0; o >>= 1) {
            pacc += __shfl_xor_sync(0xffffffffu, pacc, o);
            mxt = max(mxt, __shfl_xor_sync(0xffffffffu, mxt, o));
        }
        if (lane == 0) {
            int last = tgt[b*SS + mxt];
            float num = pacc + eng[last];
            float sm = 0.f;
#pragma unroll
            for (int i = 0; i < T; i++) sm += s.a2[1][2*i] * __expf(eng[i]);
            float den = L + __logf(sm);
            *diff_slot = num - den;
        }
    } else {
        // ================= viterbi warps (1-3) =================
        const int vl = tid - 32;
        const int col = vl >> 1;
        const bool act = col < T;
        const bool isA = !(vl & 1);
        const int jj = act ? col : 0;
        const int base = isA ? 0 : BASE_B;
        float tc[CA];
#pragma unroll
        for (int k = 0; k < CA; k++) tc[k] = trg[(base + k)*T + jj];
        float svprev = stg[jj] + eb[jj];
        float evcur = eb[T + jj];   // e[1][jj]

        for (int t = 1; t < SS; t++) {
            const int pb = (t-1) & 1, cb = t & 1;
            float evn = (t + 1 < SS) ? eb[(size_t)(t+1)*T + jj] : 0.f;
            // load my half of sv[pb]
            float svv[CA];
            const float* sp = s.sv[pb] + base;
            constexpr int C4 = CA / 4;
#pragma unroll
            for (int k = 0; k < C4; k++) {
                float4 q = *(const float4*)(sp + 4*k);
                svv[4*k+0] = q.x; svv[4*k+1] = q.y;
                svv[4*k+2] = q.z; svv[4*k+3] = q.w;
            }
#pragma unroll
            for (int r = 4*C4; r < CA; r++) svv[r] = sp[r];
            // chunked first-argmax (contiguous chunks keep lowest-index ties)
            constexpr int NCH = (CA + 6) / 7;
            float bb[NCH]; int aa[NCH];
#pragma unroll
            for (int c = 0; c < NCH; c++) { bb[c] = -1e30f; aa[c] = 0; }
#pragma unroll
            for (int k = 0; k < CA; k++) {
                float cd = svv[k] + tc[k];
                int c = k / 7;
                if (cd > bb[c]) { bb[c] = cd; aa[c] = base + k; }
            }
            float best = bb[0]; int arg = aa[0];
#pragma unroll
            for (int c = 1; c < NCH; c++)
                if (bb[c] > best) { best = bb[c]; arg = aa[c]; }
            // exchange with partner lane (A holds prefix -> wins ties)
            float bo = __shfl_xor_sync(0xffffffffu, best, 1);
            int   ao = __shfl_xor_sync(0xffffffffu, arg, 1);
            if (isA && act) {
                if (bo > best) { best = bo; arg = ao; }
                unsigned mt = (s.mword[t >> 5] >> (t & 31)) & 1u;
                float e = evcur;
                float svnew; unsigned char h;
                if (mt) { svnew = best + e; h = (unsigned char)arg; }
                else    { svnew = svprev;   h = (unsigned char)col; }
                s.sv[cb][col] = svnew;
                svprev = svnew;
                s.hist[(t-1)*T + col] = h;
            }
            evcur = evn;
            asm volatile("bar.sync 2, 96;" ::: "memory");
        }
        // backtrace (warp 1, lane 0), then coalesced write by warp 1
        if (tid == 32) {
            float bv = -1e30f; int cur = 0;
#pragma unroll
            for (int j = 0; j < T; j++) {
                float c = s.sv[1][j] + eng[j];
                if (c > bv) { bv = c; cur = j; }
            }
            s.path[SS-1] = (unsigned char)cur;
            for (int tt = SS-1; tt >= 1; tt--) {
                cur = s.hist[(tt-1)*T + cur];
                s.path[tt-1] = (unsigned char)cur;
            }
        }
        if (w == 1) {
            __syncwarp();
            for (int i = lane; i < SS; i += 32) pred[i] = (float)s.path[i];
        }
    }
}

__global__ __launch_bounds__(160) void crf_kernel(
    const float* __restrict__ st_t, const float* __restrict__ tr_t, const float* __restrict__ en_t,
    const float* __restrict__ st_p, const float* __restrict__ tr_p, const float* __restrict__ en_p,
    const int* __restrict__ tgt_t, const int* __restrict__ tgt_p,
    const int* __restrict__ mask,
    float* __restrict__ pred_out)
{
    __shared__ CrfSmem s;
    const int head = blockIdx.x >> 6;
    const int b    = blockIdx.x & 63;
    float* pred = pred_out + (size_t)head*MM + (size_t)b*SS;
    float* diff = &g_diff[head*BB + b];
    if (head == 0)
        crf_chain<TTAG>(s, st_t, tr_t, en_t, tgt_t, mask,
                        g_tag  + (size_t)b*SS*TTAG,
                        g_Etag + (size_t)b*SS*TTAG, b, pred, diff);
    else
        crf_chain<TPOS>(s, st_p, tr_p, en_p, tgt_p, mask,
                        g_pos  + (size_t)b*SS*TPOS,
                        g_Epos + (size_t)b*SS*TPOS, b, pred, diff);
}

// ============================================================
// finalize: loss = -mean(num - den) per head
// ============================================================
__global__ void finalize_kernel(float* __restrict__ out, int out_size)
{
    if (threadIdx.x == 0) {
        float s0 = 0.f, s1 = 0.f;
        for (int i = 0; i < BB; i++) { s0 += g_diff[i]; s1 += g_diff[BB + i]; }
        if (out_size > 2*MM)     out[2*MM]     = -s0 / (float)BB;
        if (out_size > 2*MM + 1) out[2*MM + 1] = -s1 / (float)BB;
    }
}

extern "C" void kernel_launch(void* const* d_in, const int* in_sizes, int n_in,
                              void* d_out, int out_size)
{
    const float* hidden = (const float*)d_in[0];
    const int*   mask   = (const int*)d_in[1];
    const int*   tgt_t  = (const int*)d_in[2];
    const int*   tgt_p  = (const int*)d_in[3];
    const float* Wt     = (const float*)d_in[4];
    const float* bt     = (const float*)d_in[5];
    const float* Wp     = (const float*)d_in[6];
    const float* bp     = (const float*)d_in[7];
    const float* st_t   = (const float*)d_in[8];
    const float* tr_t   = (const float*)d_in[9];
    const float* en_t   = (const float*)d_in[10];
    const float* st_p   = (const float*)d_in[11];
    const float* tr_p   = (const float*)d_in[12];
    const float* en_p   = (const float*)d_in[13];
    float* out = (float*)d_out;

    gemm_kernel<<<MM/128, 256>>>(hidden, Wt, bt, Wp, bp);
    expe_kernel<<<MM, 64>>>();
    crf_kernel<<<2*BB, 160>>>(st_t, tr_t, en_t, st_p, tr_p, en_p,
                              tgt_t, tgt_p, mask, out);
    finalize_kernel<<<1, 32>>>(out, out_size);
}